// round 11
// baseline (speedup 1.0000x reference)
#include <cuda_runtime.h>
#include <cuda_bf16.h>
#include <cstdint>
#include <cstring>

// einsum('bis,ie->bse') via mma.sync bf16 3-term split.
//   inputs    [B=64, I=64, S=4096] f32
//   embedding [I=64, E=64]         f32
//   out       [B=64, S=4096, E=64] f32
//
// D = Ahi*Bhi + Ahi*Blo + Alo*Bhi  (bf16, fp32 accumulate), rel err ~3.4e-6.
//
// vs round 9: A is staged into smem ALREADY SPLIT into bf16x2 k-pair fragments
// (Ahi/Alo u32 arrays). The per-fragment CVT/FSUB split chains (~160 issues +
// serial latency on the MMA critical path) move out of the mainloop into the
// LDG-covered staging phase; mainloop A traffic halves. Stride 264 keeps the
// k2-row fragment reads bank-conflict-free (8*k2+s pattern).

#define BATCH 64
#define ISZ   64
#define SEQ   4096
#define ESZ   64
#define MTILE 256        // s per CTA
#define THREADS 256

#define AP_STRIDE 264    // u32 words per k2-row: bank = (8*k2 + s) % 32 -> conflict-free
#define BS_STRIDE 72     // u32 words per k2-row for B
#define SMEM_AH_OFF 0
#define SMEM_AL_OFF (32 * AP_STRIDE * 4)                 // 33792
#define SMEM_BH_OFF (2 * 32 * AP_STRIDE * 4)             // 67584
#define SMEM_BL_OFF (SMEM_BH_OFF + 32 * BS_STRIDE * 4)
#define SMEM_TOTAL  (SMEM_BH_OFF + 2 * 32 * BS_STRIDE * 4)   // 86016 B

__device__ __forceinline__ uint32_t pack_bf2(float a, float b) {
    __nv_bfloat162 h = __floats2bfloat162_rn(a, b);  // .x -> low 16 bits
    uint32_t u; memcpy(&u, &h, 4);
    return u;
}

__device__ __forceinline__ void split_pair(float xa, float xb,
                                           uint32_t& hi, uint32_t& lo) {
    hi = pack_bf2(xa, xb);
    __nv_bfloat162 hv; memcpy(&hv, &hi, 4);
    lo = pack_bf2(xa - __bfloat162float(hv.x), xb - __bfloat162float(hv.y));
}

#define MMA_BF16(d, a0, a1, a2, a3, b0, b1) \
    asm volatile("mma.sync.aligned.m16n8k16.row.col.f32.bf16.bf16.f32 " \
        "{%0,%1,%2,%3}, {%4,%5,%6,%7}, {%8,%9}, {%0,%1,%2,%3};" \
        : "+f"((d)[0]), "+f"((d)[1]), "+f"((d)[2]), "+f"((d)[3]) \
        : "r"(a0), "r"(a1), "r"(a2), "r"(a3), "r"(b0), "r"(b1))

__global__ __launch_bounds__(THREADS, 2)
void embed_mma_kernel(const float* __restrict__ in,
                      const float* __restrict__ emb,
                      float* __restrict__ out)
{
    extern __shared__ char smem[];
    uint32_t* Ah = reinterpret_cast<uint32_t*>(smem + SMEM_AH_OFF);
    uint32_t* Al = reinterpret_cast<uint32_t*>(smem + SMEM_AL_OFF);
    uint32_t* Bh = reinterpret_cast<uint32_t*>(smem + SMEM_BH_OFF);
    uint32_t* Bl = reinterpret_cast<uint32_t*>(smem + SMEM_BL_OFF);

    const int t = threadIdx.x;
    const int b     = blockIdx.x >> 4;      // 16 s-tiles per batch
    const int stile = blockIdx.x & 15;
    const int s0    = stile * MTILE;

    // ---- stage A pre-split: Ahi/Alo[k2][s] = packed bf16 k-pair fragments ----
    // unit u = (k2, s4): 32 k2-rows x 64 float4 columns = 2048 units, 8/thread.
    {
        const float4* gin = reinterpret_cast<const float4*>(
            in + (size_t)b * (ISZ * SEQ) + s0);
        #pragma unroll
        for (int j = 0; j < 8; ++j) {
            int u  = j * THREADS + t;
            int k2 = u >> 6;                 // 0..31
            int s4 = u & 63;                 // float4 column
            float4 g0 = gin[(size_t)(2 * k2)     * (SEQ / 4) + s4];
            float4 g1 = gin[(size_t)(2 * k2 + 1) * (SEQ / 4) + s4];
            uint4 hi, lo;
            split_pair(g0.x, g1.x, hi.x, lo.x);
            split_pair(g0.y, g1.y, hi.y, lo.y);
            split_pair(g0.z, g1.z, hi.z, lo.z);
            split_pair(g0.w, g1.w, hi.w, lo.w);
            *reinterpret_cast<uint4*>(Ah + k2 * AP_STRIDE + 4 * s4) = hi;
            *reinterpret_cast<uint4*>(Al + k2 * AP_STRIDE + 4 * s4) = lo;
        }
    }
    // ---- stage B: split hi/lo, pack k-pairs: Bp[k2][e] ----
    {
        #pragma unroll
        for (int j = 0; j < 8; ++j) {
            int idx = j * THREADS + t;      // 0..2047
            int k2 = idx >> 6, e = idx & 63;
            float x0 = emb[(2 * k2) * ESZ + e];
            float x1 = emb[(2 * k2 + 1) * ESZ + e];
            uint32_t hp, lp;
            split_pair(x0, x1, hp, lp);
            Bh[k2 * BS_STRIDE + e] = hp;
            Bl[k2 * BS_STRIDE + e] = lp;
        }
    }
    __syncthreads();

    const int w    = t >> 5;
    const int lane = t & 31;
    const int r  = lane >> 2;     // 0..7
    const int cq = lane & 3;      // 0..3

    // warp covers s in [32w, 32w+32): m-tile 0 rows r/r+8, m-tile 1 at +16/+24
    const int sbase = 32 * w + r;

    float acc[2][8][4];
    #pragma unroll
    for (int mt = 0; mt < 2; ++mt)
        #pragma unroll
        for (int nt = 0; nt < 8; ++nt)
            #pragma unroll
            for (int q = 0; q < 4; ++q) acc[mt][nt][q] = 0.0f;

    #pragma unroll
    for (int ks = 0; ks < 4; ++ks) {
        const int k2 = ks * 8 + cq;         // fragment row (k-pair index)
        const uint32_t* H0 = Ah + k2 * AP_STRIDE + sbase;
        const uint32_t* H4 = Ah + (k2 + 4) * AP_STRIDE + sbase;
        const uint32_t* L0 = Al + k2 * AP_STRIDE + sbase;
        const uint32_t* L4 = Al + (k2 + 4) * AP_STRIDE + sbase;

        // A fragments straight from smem -- no conversion in the loop.
        uint32_t a0h[2], a1h[2], a2h[2], a3h[2];
        uint32_t a0l[2], a1l[2], a2l[2], a3l[2];
        a0h[0] = H0[0];  a1h[0] = H0[8];  a2h[0] = H4[0];  a3h[0] = H4[8];
        a0l[0] = L0[0];  a1l[0] = L0[8];  a2l[0] = L4[0];  a3l[0] = L4[8];
        a0h[1] = H0[16]; a1h[1] = H0[24]; a2h[1] = H4[16]; a3h[1] = H4[24];
        a0l[1] = L0[16]; a1l[1] = L0[24]; a2l[1] = L4[16]; a3l[1] = L4[24];

        const uint32_t* bh0 = Bh + (ks * 8 + cq) * BS_STRIDE + r;
        const uint32_t* bh1 = Bh + (ks * 8 + cq + 4) * BS_STRIDE + r;
        const uint32_t* bl0 = Bl + (ks * 8 + cq) * BS_STRIDE + r;
        const uint32_t* bl1 = Bl + (ks * 8 + cq + 4) * BS_STRIDE + r;

        uint32_t B0h[8], B1h[8], B0l[8], B1l[8];
        #pragma unroll
        for (int nt = 0; nt < 8; ++nt) {
            B0h[nt] = bh0[nt * 8];
            B1h[nt] = bh1[nt * 8];
            B0l[nt] = bl0[nt * 8];
            B1l[nt] = bl1[nt * 8];
        }

        #pragma unroll
        for (int nt = 0; nt < 8; ++nt) {
            MMA_BF16(acc[0][nt], a0h[0], a1h[0], a2h[0], a3h[0], B0h[nt], B1h[nt]);
            MMA_BF16(acc[0][nt], a0h[0], a1h[0], a2h[0], a3h[0], B0l[nt], B1l[nt]);
            MMA_BF16(acc[0][nt], a0l[0], a1l[0], a2l[0], a3l[0], B0h[nt], B1h[nt]);
            MMA_BF16(acc[1][nt], a0h[1], a1h[1], a2h[1], a3h[1], B0h[nt], B1h[nt]);
            MMA_BF16(acc[1][nt], a0h[1], a1h[1], a2h[1], a3h[1], B0l[nt], B1l[nt]);
            MMA_BF16(acc[1][nt], a0l[1], a1l[1], a2l[1], a3l[1], B0h[nt], B1h[nt]);
        }
    }

    // ---- epilogue: c0,c1 -> row s ; c2,c3 -> row s+8 ----
    #pragma unroll
    for (int mt = 0; mt < 2; ++mt) {
        const size_t srow = (size_t)b * SEQ + s0 + sbase + 16 * mt;
        float* orow  = out + srow * ESZ;
        float* orow8 = out + (srow + 8) * ESZ;
        #pragma unroll
        for (int nt = 0; nt < 8; ++nt) {
            *reinterpret_cast<float2*>(orow  + nt * 8 + 2 * cq) =
                make_float2(acc[mt][nt][0], acc[mt][nt][1]);
            *reinterpret_cast<float2*>(orow8 + nt * 8 + 2 * cq) =
                make_float2(acc[mt][nt][2], acc[mt][nt][3]);
        }
    }
}

extern "C" void kernel_launch(void* const* d_in, const int* in_sizes, int n_in,
                              void* d_out, int out_size)
{
    const float* in  = (const float*)d_in[0];   // [64, 64, 4096]
    const float* emb = (const float*)d_in[1];   // [64, 64]
    float* out = (float*)d_out;                 // [64, 4096, 64]

    cudaFuncSetAttribute(embed_mma_kernel,
                         cudaFuncAttributeMaxDynamicSharedMemorySize, SMEM_TOTAL);

    const int blocks = BATCH * (SEQ / MTILE);   // 64 * 16 = 1024
    embed_mma_kernel<<<blocks, THREADS, SMEM_TOTAL>>>(in, emb, out);
}

// round 12
// speedup vs baseline: 1.2231x; 1.2231x over previous
#include <cuda_runtime.h>
#include <cuda_fp16.h>
#include <cstdint>
#include <cstring>

// einsum('bis,ie->bse') via mma.sync f16 2-term split.
//   inputs    [B=64, I=64, S=4096] f32
//   embedding [I=64, E=64]         f32
//   out       [B=64, S=4096, E=64] f32
//
// D = Ahi*Bhi + Ahi*Blo   (f16 operands, fp32 accumulate)
// f16 keeps 11 mantissa bits -> dropping the A-lo terms gives rel err
// ~2-3e-4, inside the 1e-3 budget. Cuts MMA passes 3 -> 2 and removes the
// A-residual computation from the mainloop (vs the validated bf16 3-term).
//
// Structure is round-6's best shape: mt=2, nt=8, direct-LDG A operands,
// B staged hi/lo in smem, 256 threads, 2 CTAs/SM.

#define BATCH 64
#define ISZ   64
#define SEQ   4096
#define ESZ   64
#define MTILE 256        // s per CTA
#define THREADS 256

#define BS_STRIDE 72     // u32 words per k2-row; conflict-free fragment reads
#define SMEM_BH_OFF 0
#define SMEM_BL_OFF (32 * BS_STRIDE * 4)
#define SMEM_TOTAL  (2 * 32 * BS_STRIDE * 4)   // 18432 B

__device__ __forceinline__ uint32_t pack_h2(float a, float b) {
    __half2 h = __floats2half2_rn(a, b);   // .x -> low 16 bits
    uint32_t u; memcpy(&u, &h, 4);
    return u;
}

// split one f32 pair into (hi packed f16x2, lo packed f16x2)
__device__ __forceinline__ void split_pair_h(float xa, float xb,
                                             uint32_t& hi, uint32_t& lo) {
    hi = pack_h2(xa, xb);
    __half2 hv; memcpy(&hv, &hi, 4);
    lo = pack_h2(xa - __half2float(hv.x), xb - __half2float(hv.y));
}

#define MMA_F16(d, a0, a1, a2, a3, b0, b1) \
    asm volatile("mma.sync.aligned.m16n8k16.row.col.f32.f16.f16.f32 " \
        "{%0,%1,%2,%3}, {%4,%5,%6,%7}, {%8,%9}, {%0,%1,%2,%3};" \
        : "+f"((d)[0]), "+f"((d)[1]), "+f"((d)[2]), "+f"((d)[3]) \
        : "r"(a0), "r"(a1), "r"(a2), "r"(a3), "r"(b0), "r"(b1))

__global__ __launch_bounds__(THREADS, 2)
void embed_mma_kernel(const float* __restrict__ in,
                      const float* __restrict__ emb,
                      float* __restrict__ out)
{
    extern __shared__ char smem[];
    uint32_t* Bh = reinterpret_cast<uint32_t*>(smem + SMEM_BH_OFF);
    uint32_t* Bl = reinterpret_cast<uint32_t*>(smem + SMEM_BL_OFF);

    const int t = threadIdx.x;
    const int b     = blockIdx.x >> 4;      // 16 s-tiles per batch
    const int stile = blockIdx.x & 15;
    const int s0    = stile * MTILE;

    // ---- stage B: read emb f32, split f16 hi/lo, pack k-pairs ----
    // Bp[k2][e] = pack(emb[2k2][e], emb[2k2+1][e]); 32 x 64 u32 per array.
    {
        #pragma unroll
        for (int j = 0; j < 8; ++j) {
            int idx = j * THREADS + t;      // 0..2047
            int k2 = idx >> 6, e = idx & 63;
            float x0 = emb[(2 * k2) * ESZ + e];
            float x1 = emb[(2 * k2 + 1) * ESZ + e];
            uint32_t hp, lp;
            split_pair_h(x0, x1, hp, lp);
            Bh[k2 * BS_STRIDE + e] = hp;
            Bl[k2 * BS_STRIDE + e] = lp;
        }
    }
    __syncthreads();

    const int w    = t >> 5;
    const int lane = t & 31;
    const int r  = lane >> 2;     // 0..7
    const int cq = lane & 3;      // 0..3

    // warp covers s rows [s0+32w, +32): m-tile 0 at +0, m-tile 1 at +16
    const float* Ab = in + (size_t)b * (ISZ * SEQ) + s0 + 32 * w + r;

    float acc[2][8][4];
    #pragma unroll
    for (int mt = 0; mt < 2; ++mt)
        #pragma unroll
        for (int nt = 0; nt < 8; ++nt)
            #pragma unroll
            for (int q = 0; q < 4; ++q) acc[mt][nt][q] = 0.0f;

    #pragma unroll
    for (int ks = 0; ks < 4; ++ks) {
        const int ka = ks * 16 + 2 * cq;
        const float* P0 = Ab + (size_t)(ka    ) * SEQ;
        const float* P1 = Ab + (size_t)(ka + 1) * SEQ;
        const float* P8 = Ab + (size_t)(ka + 8) * SEQ;
        const float* P9 = Ab + (size_t)(ka + 9) * SEQ;

        // A loads (direct from global), both m-tiles, batched for MLP.
        const float v00 = P0[0],  v10 = P1[0],  v08 = P0[8],  v18 = P1[8];
        const float v80 = P8[0],  v90 = P9[0],  v88 = P8[8],  v98 = P9[8];
        const float u00 = P0[16], u10 = P1[16], u08 = P0[24], u18 = P1[24];
        const float u80 = P8[16], u90 = P9[16], u88 = P8[24], u98 = P9[24];

        // A hi fragments only (no residual needed with f16 2-term).
        uint32_t a0[2], a1[2], a2[2], a3[2];
        a0[0] = pack_h2(v00, v10);  a1[0] = pack_h2(v08, v18);
        a2[0] = pack_h2(v80, v90);  a3[0] = pack_h2(v88, v98);
        a0[1] = pack_h2(u00, u10);  a1[1] = pack_h2(u08, u18);
        a2[1] = pack_h2(u80, u90);  a3[1] = pack_h2(u88, u98);

        const uint32_t* bh0 = Bh + (ks * 8 + cq) * BS_STRIDE + r;
        const uint32_t* bh1 = Bh + (ks * 8 + cq + 4) * BS_STRIDE + r;
        const uint32_t* bl0 = Bl + (ks * 8 + cq) * BS_STRIDE + r;
        const uint32_t* bl1 = Bl + (ks * 8 + cq + 4) * BS_STRIDE + r;

        #pragma unroll
        for (int nt = 0; nt < 8; ++nt) {
            const uint32_t b0h = bh0[nt * 8];
            const uint32_t b1h = bh1[nt * 8];
            const uint32_t b0l = bl0[nt * 8];
            const uint32_t b1l = bl1[nt * 8];
            MMA_F16(acc[0][nt], a0[0], a1[0], a2[0], a3[0], b0h, b1h);
            MMA_F16(acc[0][nt], a0[0], a1[0], a2[0], a3[0], b0l, b1l);
            MMA_F16(acc[1][nt], a0[1], a1[1], a2[1], a3[1], b0h, b1h);
            MMA_F16(acc[1][nt], a0[1], a1[1], a2[1], a3[1], b0l, b1l);
        }
    }

    // ---- epilogue: c0,c1 -> row s ; c2,c3 -> row s+8 ----
    #pragma unroll
    for (int mt = 0; mt < 2; ++mt) {
        const size_t srow = (size_t)b * SEQ + s0 + 32 * w + 16 * mt + r;
        float* orow  = out + srow * ESZ;
        float* orow8 = out + (srow + 8) * ESZ;
        #pragma unroll
        for (int nt = 0; nt < 8; ++nt) {
            *reinterpret_cast<float2*>(orow  + nt * 8 + 2 * cq) =
                make_float2(acc[mt][nt][0], acc[mt][nt][1]);
            *reinterpret_cast<float2*>(orow8 + nt * 8 + 2 * cq) =
                make_float2(acc[mt][nt][2], acc[mt][nt][3]);
        }
    }
}

extern "C" void kernel_launch(void* const* d_in, const int* in_sizes, int n_in,
                              void* d_out, int out_size)
{
    const float* in  = (const float*)d_in[0];   // [64, 64, 4096]
    const float* emb = (const float*)d_in[1];   // [64, 64]
    float* out = (float*)d_out;                 // [64, 4096, 64]

    const int blocks = BATCH * (SEQ / MTILE);   // 64 * 16 = 1024
    embed_mma_kernel<<<blocks, THREADS, SMEM_TOTAL>>>(in, emb, out);
}